// round 15
// baseline (speedup 1.0000x reference)
#include <cuda_runtime.h>
#include <cuda_fp16.h>
#include <cstdint>

#define HW    4096
#define CH    256
#define BATCH 4

// fp16 operands / activations
__device__ __half g_xh [2ull * BATCH * HW * CH];          // LN output [side][p][c]
__device__ __half g_wh [768ull * 256];                    // [Wq|Wk|Wvo]^T: [n][k]
__device__ __half g_qh [2ull * BATCH * HW * CH];          // [z][p][c]
__device__ __half g_kh [2ull * BATCH * HW * CH];          // [z][p][c]
__device__ __half g_vth[2ull * BATCH * HW * CH];          // V'^T: [z][c][m]
__device__ __half g_eh [2ull * BATCH * HW * HW];          // E then P (in place)

// ---------------------------------------------------------------------------
__device__ __forceinline__ uint32_t smem_u32(const void* p) {
    uint32_t a;
    asm("{ .reg .u64 t; cvta.to.shared.u64 t, %1; cvt.u32.u64 %0, t; }"
        : "=r"(a) : "l"(p));
    return a;
}

__device__ __forceinline__ void mma16816(float (&c)[4], const uint32_t (&a)[4],
                                         uint32_t b0, uint32_t b1) {
    asm volatile(
        "mma.sync.aligned.m16n8k16.row.col.f32.f16.f16.f32 "
        "{%0,%1,%2,%3}, {%4,%5,%6,%7}, {%8,%9}, {%0,%1,%2,%3};"
        : "+f"(c[0]), "+f"(c[1]), "+f"(c[2]), "+f"(c[3])
        : "r"(a[0]), "r"(a[1]), "r"(a[2]), "r"(a[3]), "r"(b0), "r"(b1));
}

__device__ __forceinline__ void ldsm4(uint32_t (&r)[4], uint32_t addr) {
    asm volatile("ldmatrix.sync.aligned.m8n8.x4.shared.b16 {%0,%1,%2,%3}, [%4];"
        : "=r"(r[0]), "=r"(r[1]), "=r"(r[2]), "=r"(r[3]) : "r"(addr));
}

#define CP16(s, g) \
    asm volatile("cp.async.cg.shared.global [%0], [%1], 16;" :: "r"(s), "l"(g))
#define CP_COMMIT() asm volatile("cp.async.commit_group;")
#define CP_WAIT1()  asm volatile("cp.async.wait_group 1;")

__device__ __forceinline__ void desync() {
    unsigned bid = blockIdx.x + gridDim.x * (blockIdx.y + gridDim.y * blockIdx.z);
    unsigned ph = bid % 3u;
    if (ph) __nanosleep(ph * 600u);
}

// ---------------------------------------------------------------------------
// k4 body: B fragments first, then interleave A-row LDSM with the previous
// row's MMA burst (shortens the LDSM->MMA dependency chain per k4).
// ---------------------------------------------------------------------------
__device__ __forceinline__ void mma_k4(uint32_t aAddr, uint32_t bAddr,
                                       float (&acc)[4][4][4]) {
    uint32_t bf[2][4];
    ldsm4(bf[0], bAddr);
    ldsm4(bf[1], bAddr + 16 * 144);
    uint32_t af0[4], af1[4];
    ldsm4(af0, aAddr);
    #pragma unroll
    for (int i = 0; i < 4; i++) {
        uint32_t (&cur)[4] = (i & 1) ? af1 : af0;
        uint32_t (&nxt)[4] = (i & 1) ? af0 : af1;
        if (i < 3) ldsm4(nxt, aAddr + (i + 1) * 16 * 144);
        #pragma unroll
        for (int j = 0; j < 4; j++)
            mma16816(acc[i][j], cur, bf[j >> 1][(j & 1) * 2],
                     bf[j >> 1][(j & 1) * 2 + 1]);
    }
}

// ---------------------------------------------------------------------------
// GEMM core: CTA 128x128, k-chunk 64 halfs, 3-stage cp.async pipeline,
// ldmatrix fragments. 256 threads = 8 warps (2m x 4n), warp tile 64x32.
// smem stage: (128 A + 128 B rows) x 144B = 36864 B; 3 stages = 108 KB.
// 2 CTAs/SM. One wait+sync per 64 k-steps; 4-phase warp-staggered ks order.
// ---------------------------------------------------------------------------
#define STG_B    36864
#define SMEM_MMA 110592

template <int NCH>   // number of k32 chunks; must be even
__device__ __forceinline__ void gemm_core(const __half* __restrict__ Ag,
                                          const __half* __restrict__ Bg,
                                          int ldA, int ldB, uint32_t smb,
                                          float (&acc)[4][4][4]) {
    const int tid  = threadIdx.x;
    const int lane = tid & 31, wid = tid >> 5;
    const int wm = wid >> 2, wn = wid & 3;

    const int lr = tid >> 3;                 // load row 0..31
    const int lc = tid & 7;                  // 16B column 0..7
    const __half* agp = Ag + (size_t)lr * ldA + lc * 8;
    const __half* bgp = Bg + (size_t)lr * ldB + lc * 8;

    const uint32_t sA = smb + lr * 144 + lc * 16;
    const uint32_t sB = sA + 128 * 144;

    auto issue = [&](int s, int c64) {
        const uint32_t off = s * STG_B;
        const __half* a0 = agp + (size_t)c64 * 64;
        const __half* b0 = bgp + (size_t)c64 * 64;
        #pragma unroll
        for (int r = 0; r < 4; r++) {
            CP16(sA + off + r * 32 * 144, a0 + (size_t)(r * 32) * ldA);
            CP16(sB + off + r * 32 * 144, b0 + (size_t)(r * 32) * ldB);
        }
        CP_COMMIT();
    };

    issue(0, 0); issue(1, 1);

    const uint32_t aBase = smb + (wm * 64 + (lane & 15)) * 144 + (lane >> 4) * 16;
    const uint32_t bBase = smb + 128 * 144 +
        (wn * 32 + (lane & 7) + ((lane >> 4) << 3)) * 144 + ((lane >> 3) & 1) * 16;

    const int NC64 = NCH / 2;
    #pragma unroll 3
    for (int c = 0; c < NC64; c++) {
        const int stg = c % 3;
        CP_WAIT1();
        __syncthreads();
        const uint32_t off = stg * STG_B;
        if (c + 2 < NC64) issue((c + 2) % 3, c + 2);
        else CP_COMMIT();                 // keep group count uniform
        #pragma unroll
        for (int k4 = 0; k4 < 4; k4++) {
            const int ks = (k4 + wid) & 3;      // 4-phase warp stagger
            mma_k4(aBase + off + ks * 32, bBase + off + ks * 32, acc);
        }
    }
}

// ---------------------------------------------------------------------------
// Kernel 1: LayerNorm over channels with transpose -> fp16 [side][p][c]
// grid (128, 4, 2)
// ---------------------------------------------------------------------------
__global__ __launch_bounds__(256) void ln_kernel(const float* __restrict__ xl,
                                                 const float* __restrict__ xr,
                                                 const float* __restrict__ g1,
                                                 const float* __restrict__ b1,
                                                 const float* __restrict__ g2,
                                                 const float* __restrict__ b2) {
    int side = blockIdx.z;
    const float* x  = side ? xr : xl;
    const float* gm = side ? g2 : g1;
    const float* bt = side ? b2 : b1;
    int b  = blockIdx.y;
    int p0 = blockIdx.x << 5;
    int tid = threadIdx.x, lane = tid & 31, warp = tid >> 5;

    __shared__ float tile[CH][33];
    __shared__ float red[2][8][32];
    __shared__ float mu_s[32], rs_s[32];

    #pragma unroll 4
    for (int i = 0; i < 32; i++) {
        int c = (warp << 5) + i;
        tile[c][lane] = x[((size_t)b * CH + c) * HW + p0 + lane];
    }
    __syncthreads();

    {
        int pl = tid & 31, seg = tid >> 5;
        float s = 0.f, s2 = 0.f;
        #pragma unroll 8
        for (int c = seg * 32; c < seg * 32 + 32; c++) {
            float v = tile[c][pl];
            s += v; s2 += v * v;
        }
        red[0][seg][pl] = s;
        red[1][seg][pl] = s2;
    }
    __syncthreads();
    if (tid < 32) {
        float S = 0.f, S2 = 0.f;
        #pragma unroll
        for (int g = 0; g < 8; g++) { S += red[0][g][tid]; S2 += red[1][g][tid]; }
        float mu  = S * (1.f / 256.f);
        float var = S2 * (1.f / 256.f) - mu * mu;
        mu_s[tid] = mu;
        rs_s[tid] = rsqrtf(var + 1e-5f);
    }
    __syncthreads();

    __half* xh = g_xh + ((size_t)side << 22);
    #pragma unroll
    for (int pp = warp * 4; pp < warp * 4 + 4; pp++) {
        float mu = mu_s[pp], rs = rs_s[pp];
        #pragma unroll
        for (int c = lane; c < CH; c += 32) {
            float v = (tile[c][pp] - mu) * rs * gm[c] + bt[c];
            xh[((size_t)(b * HW + p0 + pp)) * 256 + c] = __float2half_rn(v);
        }
    }
}

// ---------------------------------------------------------------------------
// Kernel 2 (merged): blocks <512: g_wh[n][k] = Wq/Wk[k][n] transpose+convert.
// blocks >=512: Wvo = Wv @ Wo rows, stored transposed at g_wh[512+n][k].
// grid 576, block 256.
// ---------------------------------------------------------------------------
__global__ __launch_bounds__(256) void wprep_kernel(const float* __restrict__ Wq,
                                                    const float* __restrict__ Wk,
                                                    const float* __restrict__ Wv,
                                                    const float* __restrict__ Wo) {
    const int blk = blockIdx.x;
    if (blk < 512) {
        int n = blk, k = threadIdx.x;
        const float* W = (n < 256) ? Wq : Wk;
        g_wh[(size_t)n * 256 + k] = __float2half_rn(W[(size_t)k * 256 + (n & 255)]);
        return;
    }
    __shared__ float wv4[4][256];
    const int k0 = (blk - 512) << 2;
    const int n  = threadIdx.x;
    #pragma unroll
    for (int i = 0; i < 4; i++)
        wv4[i][n] = Wv[(size_t)(k0 + i) * 256 + n];
    __syncthreads();

    float a0 = 0.f, a1 = 0.f, a2 = 0.f, a3 = 0.f;
    #pragma unroll 8
    for (int m = 0; m < 256; m++) {
        float w = Wo[(size_t)m * 256 + n];
        a0 += wv4[0][m] * w;
        a1 += wv4[1][m] * w;
        a2 += wv4[2][m] * w;
        a3 += wv4[3][m] * w;
    }
    __half2 h01 = __floats2half2_rn(a0, a1);
    __half2 h23 = __floats2half2_rn(a2, a3);
    uint2 v;
    v.x = *(uint32_t*)&h01;
    v.y = *(uint32_t*)&h23;
    *(uint2*)(g_wh + (size_t)(512 + n) * 256 + k0) = v;
}

// ---------------------------------------------------------------------------
// Kernel 3: fused QKV' GEMM. grid (6, 128, 2). N: [0,256)Q [256,512)K [512,768)V'
// ---------------------------------------------------------------------------
__global__ __launch_bounds__(256, 2) void qkv_mma() {
    extern __shared__ char smraw[];
    const uint32_t smb = smem_u32(smraw);
    desync();
    const int side = blockIdx.z;
    const int m0 = blockIdx.y << 7, n0 = blockIdx.x << 7;

    const __half* Ag = g_xh + ((size_t)side << 22) + (size_t)m0 * 256;
    const __half* Bg = g_wh + (size_t)n0 * 256;

    float acc[4][4][4] = {};
    gemm_core<8>(Ag, Bg, 256, 256, smb, acc);

    const int tid = threadIdx.x, wid = tid >> 5, lane = tid & 31;
    const int wm = wid >> 2, wn = wid & 3;
    const int qr = lane >> 2, qc = lane & 3;

    const int z  = side * 4 + (m0 >> 12);
    const int pb = m0 & 4095;

    if (n0 < 512) {
        __syncthreads();
        __half* st = (__half*)smraw;   // [128 m][136 pitch]
        #pragma unroll
        for (int i = 0; i < 4; i++) {
            int ml = wm * 64 + i * 16 + qr;
            #pragma unroll
            for (int j = 0; j < 4; j++) {
                int nl = wn * 32 + j * 8 + qc * 2;
                *(__half2*)(st + (size_t)ml * 136 + nl) =
                    __floats2half2_rn(acc[i][j][0], acc[i][j][1]);
                *(__half2*)(st + (size_t)(ml + 8) * 136 + nl) =
                    __floats2half2_rn(acc[i][j][2], acc[i][j][3]);
            }
        }
        __syncthreads();
        __half* dst = ((n0 >> 8) == 0 ? g_qh : g_kh) + ((size_t)z << 20);
        const int nloc = n0 & 255;
        for (int idx = tid; idx < 128 * 16; idx += 256) {
            int r = idx >> 4, g = idx & 15;
            *(uint4*)(dst + (size_t)(pb + r) * 256 + nloc + g * 8) =
                *(const uint4*)(st + (size_t)r * 136 + g * 8);
        }
    } else {
        // V': transpose via smem -> g_vth[z][c][m]
        __syncthreads();
        __half* st = (__half*)smraw;   // [128 n][136 m]
        #pragma unroll
        for (int i = 0; i < 4; i++) {
            int ml = wm * 64 + i * 16 + qr;
            #pragma unroll
            for (int j = 0; j < 4; j++) {
                int nl = wn * 32 + j * 8 + qc * 2;
                st[(size_t)nl * 136 + ml]           = __float2half_rn(acc[i][j][0]);
                st[(size_t)(nl + 1) * 136 + ml]     = __float2half_rn(acc[i][j][1]);
                st[(size_t)nl * 136 + ml + 8]       = __float2half_rn(acc[i][j][2]);
                st[(size_t)(nl + 1) * 136 + ml + 8] = __float2half_rn(acc[i][j][3]);
            }
        }
        __syncthreads();
        const int cv0 = n0 - 512;
        __half* dst = g_vth + ((size_t)z << 20) + pb;
        for (int idx = tid; idx < 128 * 16; idx += 256) {
            int r = idx >> 4, g = idx & 15;
            uint4 v = *(const uint4*)(st + (size_t)r * 136 + g * 8);
            *(uint4*)(dst + (size_t)(cv0 + r) * 4096 + g * 8) = v;
        }
    }
}

// ---------------------------------------------------------------------------
// Kernel 4 (FUSED scores + softmax-normalize): one CTA does all 4 batches of
// its (m0,n0,side) tile in one 16-chunk pipeline, then normalizes in place.
// grid (32, 32, 2)
// ---------------------------------------------------------------------------
__global__ __launch_bounds__(256, 2) void scores_mma() {
    extern __shared__ char smraw[];
    const uint32_t smb = smem_u32(smraw);
    desync();
    const int side = blockIdx.z;
    const int m0 = blockIdx.y << 7, n0 = blockIdx.x << 7;

    const int tid = threadIdx.x, lane = tid & 31, wid = tid >> 5;
    const int wm = wid >> 2, wn = wid & 3;
    const int qr = lane >> 2, qc = lane & 3;

    const int lr = tid >> 3, lc = tid & 7;
    const size_t aoff = (size_t)(m0 + lr) * 256 + lc * 8;
    const size_t boff = (size_t)(n0 + lr) * 256 + lc * 8;
    const __half* qbase = g_qh + ((size_t)(side * 4) << 20);
    const __half* kbase = g_kh + ((size_t)((side ^ 1) * 4) << 20);

    const uint32_t sA = smb + lr * 144 + lc * 16;
    const uint32_t sB = sA + 128 * 144;

    auto issue = [&](int s, int c) {
        const uint32_t off = s * STG_B;
        const int b = c >> 2, ko = (c & 3) << 6;
        const __half* a0 = qbase + ((size_t)b << 20) + aoff + ko;
        const __half* b0 = kbase + ((size_t)b << 20) + boff + ko;
        #pragma unroll
        for (int r = 0; r < 4; r++) {
            CP16(sA + off + r * 32 * 144, a0 + (size_t)(r * 32) * 256);
            CP16(sB + off + r * 32 * 144, b0 + (size_t)(r * 32) * 256);
        }
        CP_COMMIT();
    };

    issue(0, 0); issue(1, 1);

    const uint32_t aBase = smb + (wm * 64 + (lane & 15)) * 144 + (lane >> 4) * 16;
    const uint32_t bBase = smb + 128 * 144 +
        (wn * 32 + (lane & 7) + ((lane >> 4) << 3)) * 144 + ((lane >> 3) & 1) * 16;

    const float scale = 0.0625f;
    float acc[4][4][4];

    int stg = 0, nxt = 2;
    #pragma unroll 1
    for (int c = 0; c < 16; c++) {
        CP_WAIT1();
        __syncthreads();      // also orders previous epilogue's smem use vs reuse
        const uint32_t off = stg * STG_B;
        if (c + 2 < 16) issue(nxt, c + 2);
        else CP_COMMIT();                 // keep group count uniform
        if (++stg == 3) stg = 0;
        if (++nxt == 3) nxt = 0;

        if ((c & 3) == 0) {
            #pragma unroll
            for (int i = 0; i < 4; i++)
                #pragma unroll
                for (int j = 0; j < 4; j++)
                    #pragma unroll
                    for (int t = 0; t < 4; t++) acc[i][j][t] = 0.f;
        }

        #pragma unroll
        for (int k4 = 0; k4 < 4; k4++) {
            const int ks = (k4 + wid) & 3;      // 4-phase warp stagger
            mma_k4(aBase + off + ks * 32, bBase + off + ks * 32, acc);
        }

        if ((c & 3) == 3) {
            // epilogue for batch b: exp + stage into the just-freed pipe stage
            const int b = c >> 2;
            const int fs = c % 3;          // stage consumed this iteration
            __half* stb = (__half*)(smraw + fs * STG_B);   // [128 m][136 pitch]
            __syncthreads();               // all warps done with stage fs
            #pragma unroll
            for (int i = 0; i < 4; i++) {
                int ml = wm * 64 + i * 16 + qr;
                #pragma unroll
                for (int j = 0; j < 4; j++) {
                    int nl = wn * 32 + j * 8 + qc * 2;
                    *(__half2*)(stb + (size_t)ml * 136 + nl) =
                        __floats2half2_rn(__expf(acc[i][j][0] * scale),
                                          __expf(acc[i][j][1] * scale));
                    *(__half2*)(stb + (size_t)(ml + 8) * 136 + nl) =
                        __floats2half2_rn(__expf(acc[i][j][2] * scale),
                                          __expf(acc[i][j][3] * scale));
                }
            }
            __syncthreads();
            __half* Ce = g_eh + ((size_t)(side * 4 + b) << 24);
            for (int idx = tid; idx < 128 * 16; idx += 256) {
                int r = idx >> 4, g = idx & 15;
                *(uint4*)(Ce + (size_t)(m0 + r) * 4096 + n0 + g * 8) =
                    *(const uint4*)(stb + (size_t)r * 136 + g * 8);
            }
        }
    }

    // in-place normalize: P_b = E_b / sum_b E_b over this CTA's own 4 tiles
    __syncthreads();
    __half* Eb = g_eh + ((size_t)(side * 4) << 24);
    #pragma unroll 1
    for (int s8 = 0; s8 < 8; s8++) {
        int idx = s8 * 256 + tid;
        int r = idx >> 4, g = idx & 15;
        __half* p = Eb + (size_t)(m0 + r) * 4096 + n0 + g * 8;
        uint4 e0 = *(const uint4*)(p);
        uint4 e1 = *(const uint4*)(p + (1ull << 24));
        uint4 e2 = *(const uint4*)(p + (2ull << 24));
        uint4 e3 = *(const uint4*)(p + (3ull << 24));
        #pragma unroll
        for (int t = 0; t < 4; t++) {
            float2 f0 = __half22float2(((const __half2*)&e0)[t]);
            float2 f1 = __half22float2(((const __half2*)&e1)[t]);
            float2 f2 = __half22float2(((const __half2*)&e2)[t]);
            float2 f3 = __half22float2(((const __half2*)&e3)[t]);
            float rx = 1.0f / (f0.x + f1.x + f2.x + f3.x);
            float ry = 1.0f / (f0.y + f1.y + f2.y + f3.y);
            ((__half2*)&e0)[t] = __floats2half2_rn(f0.x * rx, f0.y * ry);
            ((__half2*)&e1)[t] = __floats2half2_rn(f1.x * rx, f1.y * ry);
            ((__half2*)&e2)[t] = __floats2half2_rn(f2.x * rx, f2.y * ry);
            ((__half2*)&e3)[t] = __floats2half2_rn(f3.x * rx, f3.y * ry);
        }
        *(uint4*)(p)                = e0;
        *(uint4*)(p + (1ull << 24)) = e1;
        *(uint4*)(p + (2ull << 24)) = e2;
        *(uint4*)(p + (3ull << 24)) = e3;
    }
}

// ---------------------------------------------------------------------------
// Kernel 5 (FINAL): out = x + P @ V'   (V' has Wo folded in)
// grid (2, 32, 8), K = 4096. Epilogue: fp32 transpose + residual -> d_out.
// ---------------------------------------------------------------------------
__global__ __launch_bounds__(256, 2) void pv_mma(const float* __restrict__ xl,
                                                 const float* __restrict__ xr,
                                                 float* __restrict__ outp) {
    extern __shared__ char smraw[];
    const uint32_t smb = smem_u32(smraw);
    desync();
    const int z = blockIdx.z;
    const int m0 = blockIdx.y << 7, n0 = blockIdx.x << 7;

    const __half* Ag = g_eh  + ((size_t)z << 24) + (size_t)m0 * 4096;
    const __half* Bg = g_vth + ((size_t)z << 20) + (size_t)n0 * 4096;

    float acc[4][4][4] = {};
    gemm_core<128>(Ag, Bg, 4096, 4096, smb, acc);

    const int tid = threadIdx.x, wid = tid >> 5, lane = tid & 31;
    const int wm = wid >> 2, wn = wid & 3;
    const int qr = lane >> 2, qc = lane & 3;

    // stage fp32 through smem (transpose), then residual add + store
    __syncthreads();
    float* st = (float*)smraw;   // [128 m][129]
    #pragma unroll
    for (int i = 0; i < 4; i++) {
        int ml = wm * 64 + i * 16 + qr;
        #pragma unroll
        for (int j = 0; j < 4; j++) {
            int nl = wn * 32 + j * 8 + qc * 2;
            st[(size_t)ml * 129 + nl]           = acc[i][j][0];
            st[(size_t)ml * 129 + nl + 1]       = acc[i][j][1];
            st[(size_t)(ml + 8) * 129 + nl]     = acc[i][j][2];
            st[(size_t)(ml + 8) * 129 + nl + 1] = acc[i][j][3];
        }
    }
    __syncthreads();

    const int side = z >> 2, b = z & 3;
    const float* x = side ? xr : xl;
    float* op = outp + ((size_t)side << 22);
    for (int idx = tid; idx < 128 * 128; idx += 256) {
        int cl = idx >> 7, pl = idx & 127;
        size_t off = ((size_t)b * 256 + n0 + cl) * 4096 + m0 + pl;
        op[off] = x[off] + st[(size_t)pl * 129 + cl];
    }
}

// ---------------------------------------------------------------------------
extern "C" void kernel_launch(void* const* d_in, const int* in_sizes, int n_in,
                              void* d_out, int out_size) {
    const float* x_l = (const float*)d_in[0];
    const float* x_r = (const float*)d_in[1];
    const float* Wq  = (const float*)d_in[2];
    const float* Wk  = (const float*)d_in[3];
    const float* Wv  = (const float*)d_in[4];
    const float* Wo  = (const float*)d_in[5];
    const float* g1  = (const float*)d_in[6];
    const float* b1  = (const float*)d_in[7];
    const float* g2  = (const float*)d_in[8];
    const float* b2  = (const float*)d_in[9];
    float* out = (float*)d_out;

    cudaFuncSetAttribute(qkv_mma,    cudaFuncAttributeMaxDynamicSharedMemorySize, SMEM_MMA);
    cudaFuncSetAttribute(scores_mma, cudaFuncAttributeMaxDynamicSharedMemorySize, SMEM_MMA);
    cudaFuncSetAttribute(pv_mma,     cudaFuncAttributeMaxDynamicSharedMemorySize, SMEM_MMA);

    // 1) LayerNorm -> fp16 [p][c]; weight prep (Wq,Wk transpose + Wvo=Wv@Wo)
    ln_kernel<<<dim3(HW / 32, BATCH, 2), 256>>>(x_l, x_r, g1, b1, g2, b2);
    wprep_kernel<<<576, 256>>>(Wq, Wk, Wv, Wo);

    // 2) fused Q/K/V' projections (V' transposed)
    qkv_mma<<<dim3(6, 128, 2), 256, SMEM_MMA>>>();

    // 3) fused scores + batch-softmax normalize (writes P in place)
    scores_mma<<<dim3(32, 32, 2), 256, SMEM_MMA>>>();

    // 4) out = x + P @ V'  (final kernel; residual + transpose epilogue)
    pv_mma<<<dim3(2, 32, 8), 256, SMEM_MMA>>>(x_l, x_r, out);
}

// round 17
// speedup vs baseline: 1.0186x; 1.0186x over previous
#include <cuda_runtime.h>
#include <cuda_fp16.h>
#include <cstdint>

#define HW    4096
#define CH    256
#define BATCH 4

// fp16 operands / activations
__device__ __half g_xh [2ull * BATCH * HW * CH];          // LN output [side][p][c]
__device__ __half g_wh [768ull * 256];                    // [Wq|Wk|Wvo]^T: [n][k]
__device__ __half g_qh [2ull * BATCH * HW * CH];          // [z][p][c]  (pre-scaled by 2^-4)
__device__ __half g_kh [2ull * BATCH * HW * CH];          // [z][p][c]
__device__ __half g_vth[2ull * BATCH * HW * CH];          // V'^T: [z][c][m]
__device__ __half g_eh [2ull * BATCH * HW * HW];          // E then P (in place)

// ---------------------------------------------------------------------------
__device__ __forceinline__ uint32_t smem_u32(const void* p) {
    uint32_t a;
    asm("{ .reg .u64 t; cvta.to.shared.u64 t, %1; cvt.u32.u64 %0, t; }"
        : "=r"(a) : "l"(p));
    return a;
}

__device__ __forceinline__ void mma16816(float (&c)[4], const uint32_t (&a)[4],
                                         uint32_t b0, uint32_t b1) {
    asm volatile(
        "mma.sync.aligned.m16n8k16.row.col.f32.f16.f16.f32 "
        "{%0,%1,%2,%3}, {%4,%5,%6,%7}, {%8,%9}, {%0,%1,%2,%3};"
        : "+f"(c[0]), "+f"(c[1]), "+f"(c[2]), "+f"(c[3])
        : "r"(a[0]), "r"(a[1]), "r"(a[2]), "r"(a[3]), "r"(b0), "r"(b1));
}

__device__ __forceinline__ void ldsm4(uint32_t (&r)[4], uint32_t addr) {
    asm volatile("ldmatrix.sync.aligned.m8n8.x4.shared.b16 {%0,%1,%2,%3}, [%4];"
        : "=r"(r[0]), "=r"(r[1]), "=r"(r[2]), "=r"(r[3]) : "r"(addr));
}

#define CP16(s, g) \
    asm volatile("cp.async.cg.shared.global [%0], [%1], 16;" :: "r"(s), "l"(g))
#define CP_COMMIT() asm volatile("cp.async.commit_group;")
#define CP_WAIT1()  asm volatile("cp.async.wait_group 1;")

__device__ __forceinline__ void desync() {
    unsigned bid = blockIdx.x + gridDim.x * (blockIdx.y + gridDim.y * blockIdx.z);
    unsigned ph = bid % 3u;
    if (ph) __nanosleep(ph * 600u);
}

// ---------------------------------------------------------------------------
// k4 body: B fragments first, then interleave A-row LDSM with MMA bursts.
// ---------------------------------------------------------------------------
__device__ __forceinline__ void mma_k4(uint32_t aAddr, uint32_t bAddr,
                                       float (&acc)[4][4][4]) {
    uint32_t bf[2][4];
    ldsm4(bf[0], bAddr);
    ldsm4(bf[1], bAddr + 16 * 144);
    uint32_t af0[4], af1[4];
    ldsm4(af0, aAddr);
    #pragma unroll
    for (int i = 0; i < 4; i++) {
        uint32_t (&cur)[4] = (i & 1) ? af1 : af0;
        uint32_t (&nxt)[4] = (i & 1) ? af0 : af1;
        if (i < 3) ldsm4(nxt, aAddr + (i + 1) * 16 * 144);
        #pragma unroll
        for (int j = 0; j < 4; j++)
            mma16816(acc[i][j], cur, bf[j >> 1][(j & 1) * 2],
                     bf[j >> 1][(j & 1) * 2 + 1]);
    }
}

// ---------------------------------------------------------------------------
// GEMM core: CTA 128x128, k-chunk 64 halfs, 3-stage cp.async pipeline.
// 256 threads = 8 warps (2m x 4n), warp tile 64x32. 2 CTAs/SM.
// ---------------------------------------------------------------------------
#define STG_B    36864
#define SMEM_MMA 110592

template <int NCH>
__device__ __forceinline__ void gemm_core(const __half* __restrict__ Ag,
                                          const __half* __restrict__ Bg,
                                          int ldA, int ldB, uint32_t smb,
                                          float (&acc)[4][4][4]) {
    const int tid  = threadIdx.x;
    const int lane = tid & 31, wid = tid >> 5;
    const int wm = wid >> 2, wn = wid & 3;

    const int lr = tid >> 3;
    const int lc = tid & 7;
    const __half* agp = Ag + (size_t)lr * ldA + lc * 8;
    const __half* bgp = Bg + (size_t)lr * ldB + lc * 8;

    const uint32_t sA = smb + lr * 144 + lc * 16;
    const uint32_t sB = sA + 128 * 144;

    auto issue = [&](int s, int c64) {
        const uint32_t off = s * STG_B;
        const __half* a0 = agp + (size_t)c64 * 64;
        const __half* b0 = bgp + (size_t)c64 * 64;
        #pragma unroll
        for (int r = 0; r < 4; r++) {
            CP16(sA + off + r * 32 * 144, a0 + (size_t)(r * 32) * ldA);
            CP16(sB + off + r * 32 * 144, b0 + (size_t)(r * 32) * ldB);
        }
        CP_COMMIT();
    };

    issue(0, 0); issue(1, 1);

    const uint32_t aBase = smb + (wm * 64 + (lane & 15)) * 144 + (lane >> 4) * 16;
    const uint32_t bBase = smb + 128 * 144 +
        (wn * 32 + (lane & 7) + ((lane >> 4) << 3)) * 144 + ((lane >> 3) & 1) * 16;

    const int NC64 = NCH / 2;
    #pragma unroll 3
    for (int c = 0; c < NC64; c++) {
        const int stg = c % 3;
        CP_WAIT1();
        __syncthreads();
        const uint32_t off = stg * STG_B;
        if (c + 2 < NC64) issue((c + 2) % 3, c + 2);
        else CP_COMMIT();
        #pragma unroll
        for (int k4 = 0; k4 < 4; k4++) {
            const int ks = (k4 + wid) & 3;
            mma_k4(aBase + off + ks * 32, bBase + off + ks * 32, acc);
        }
    }
}

// ---------------------------------------------------------------------------
// Kernel 1: LayerNorm over channels with transpose -> fp16 [side][p][c]
// ---------------------------------------------------------------------------
__global__ __launch_bounds__(256) void ln_kernel(const float* __restrict__ xl,
                                                 const float* __restrict__ xr,
                                                 const float* __restrict__ g1,
                                                 const float* __restrict__ b1,
                                                 const float* __restrict__ g2,
                                                 const float* __restrict__ b2) {
    int side = blockIdx.z;
    const float* x  = side ? xr : xl;
    const float* gm = side ? g2 : g1;
    const float* bt = side ? b2 : b1;
    int b  = blockIdx.y;
    int p0 = blockIdx.x << 5;
    int tid = threadIdx.x, lane = tid & 31, warp = tid >> 5;

    __shared__ float tile[CH][33];
    __shared__ float red[2][8][32];
    __shared__ float mu_s[32], rs_s[32];

    #pragma unroll 4
    for (int i = 0; i < 32; i++) {
        int c = (warp << 5) + i;
        tile[c][lane] = x[((size_t)b * CH + c) * HW + p0 + lane];
    }
    __syncthreads();

    {
        int pl = tid & 31, seg = tid >> 5;
        float s = 0.f, s2 = 0.f;
        #pragma unroll 8
        for (int c = seg * 32; c < seg * 32 + 32; c++) {
            float v = tile[c][pl];
            s += v; s2 += v * v;
        }
        red[0][seg][pl] = s;
        red[1][seg][pl] = s2;
    }
    __syncthreads();
    if (tid < 32) {
        float S = 0.f, S2 = 0.f;
        #pragma unroll
        for (int g = 0; g < 8; g++) { S += red[0][g][tid]; S2 += red[1][g][tid]; }
        float mu  = S * (1.f / 256.f);
        float var = S2 * (1.f / 256.f) - mu * mu;
        mu_s[tid] = mu;
        rs_s[tid] = rsqrtf(var + 1e-5f);
    }
    __syncthreads();

    __half* xh = g_xh + ((size_t)side << 22);
    #pragma unroll
    for (int pp = warp * 4; pp < warp * 4 + 4; pp++) {
        float mu = mu_s[pp], rs = rs_s[pp];
        #pragma unroll
        for (int c = lane; c < CH; c += 32) {
            float v = (tile[c][pp] - mu) * rs * gm[c] + bt[c];
            xh[((size_t)(b * HW + p0 + pp)) * 256 + c] = __float2half_rn(v);
        }
    }
}

// ---------------------------------------------------------------------------
// Kernel 2 (merged weight prep)
// ---------------------------------------------------------------------------
__global__ __launch_bounds__(256) void wprep_kernel(const float* __restrict__ Wq,
                                                    const float* __restrict__ Wk,
                                                    const float* __restrict__ Wv,
                                                    const float* __restrict__ Wo) {
    const int blk = blockIdx.x;
    if (blk < 512) {
        int n = blk, k = threadIdx.x;
        const float* W = (n < 256) ? Wq : Wk;
        g_wh[(size_t)n * 256 + k] = __float2half_rn(W[(size_t)k * 256 + (n & 255)]);
        return;
    }
    __shared__ float wv4[4][256];
    const int k0 = (blk - 512) << 2;
    const int n  = threadIdx.x;
    #pragma unroll
    for (int i = 0; i < 4; i++)
        wv4[i][n] = Wv[(size_t)(k0 + i) * 256 + n];
    __syncthreads();

    float a0 = 0.f, a1 = 0.f, a2 = 0.f, a3 = 0.f;
    #pragma unroll 8
    for (int m = 0; m < 256; m++) {
        float w = Wo[(size_t)m * 256 + n];
        a0 += wv4[0][m] * w;
        a1 += wv4[1][m] * w;
        a2 += wv4[2][m] * w;
        a3 += wv4[3][m] * w;
    }
    __half2 h01 = __floats2half2_rn(a0, a1);
    __half2 h23 = __floats2half2_rn(a2, a3);
    uint2 v;
    v.x = *(uint32_t*)&h01;
    v.y = *(uint32_t*)&h23;
    *(uint2*)(g_wh + (size_t)(512 + n) * 256 + k0) = v;
}

// ---------------------------------------------------------------------------
// Kernel 3: fused QKV' GEMM. grid (6, 128, 2).
// Q tiles are n0 in {0,128}: scaled by 2^-4 (exact) to fold the softmax scale.
// ---------------------------------------------------------------------------
__global__ __launch_bounds__(256, 2) void qkv_mma() {
    extern __shared__ char smraw[];
    const uint32_t smb = smem_u32(smraw);
    desync();
    const int side = blockIdx.z;
    const int m0 = blockIdx.y << 7, n0 = blockIdx.x << 7;

    const __half* Ag = g_xh + ((size_t)side << 22) + (size_t)m0 * 256;
    const __half* Bg = g_wh + (size_t)n0 * 256;

    float acc[4][4][4] = {};
    gemm_core<8>(Ag, Bg, 256, 256, smb, acc);

    const int tid = threadIdx.x, wid = tid >> 5, lane = tid & 31;
    const int wm = wid >> 2, wn = wid & 3;
    const int qr = lane >> 2, qc = lane & 3;

    const int z  = side * 4 + (m0 >> 12);
    const int pb = m0 & 4095;

    if (n0 < 512) {
        const float qs = (n0 < 256) ? 0.0625f : 1.0f;   // Q tiles: n0 in {0,128}
        __syncthreads();
        __half* st = (__half*)smraw;   // [128 m][136 pitch]
        #pragma unroll
        for (int i = 0; i < 4; i++) {
            int ml = wm * 64 + i * 16 + qr;
            #pragma unroll
            for (int j = 0; j < 4; j++) {
                int nl = wn * 32 + j * 8 + qc * 2;
                *(__half2*)(st + (size_t)ml * 136 + nl) =
                    __floats2half2_rn(acc[i][j][0] * qs, acc[i][j][1] * qs);
                *(__half2*)(st + (size_t)(ml + 8) * 136 + nl) =
                    __floats2half2_rn(acc[i][j][2] * qs, acc[i][j][3] * qs);
            }
        }
        __syncthreads();
        __half* dst = ((n0 >> 8) == 0 ? g_qh : g_kh) + ((size_t)z << 20);
        {
            const int r0 = tid >> 4, g = tid & 15;
            const __half* sp = st + (size_t)r0 * 136 + g * 8;
            __half* dp = dst + (size_t)(pb + r0) * 256 + (n0 & 255) + g * 8;
            #pragma unroll
            for (int it = 0; it < 8; it++) {
                *(uint4*)dp = *(const uint4*)sp;
                sp += 16 * 136;
                dp += 16 * 256;
            }
        }
    } else {
        // V': transpose via smem -> g_vth[z][c][m]
        __syncthreads();
        __half* st = (__half*)smraw;   // [128 n][136 m]
        #pragma unroll
        for (int i = 0; i < 4; i++) {
            int ml = wm * 64 + i * 16 + qr;
            #pragma unroll
            for (int j = 0; j < 4; j++) {
                int nl = wn * 32 + j * 8 + qc * 2;
                st[(size_t)nl * 136 + ml]           = __float2half_rn(acc[i][j][0]);
                st[(size_t)(nl + 1) * 136 + ml]     = __float2half_rn(acc[i][j][1]);
                st[(size_t)nl * 136 + ml + 8]       = __float2half_rn(acc[i][j][2]);
                st[(size_t)(nl + 1) * 136 + ml + 8] = __float2half_rn(acc[i][j][3]);
            }
        }
        __syncthreads();
        {
            const int r0 = tid >> 4, g = tid & 15;
            const __half* sp = st + (size_t)r0 * 136 + g * 8;
            __half* dp = g_vth + ((size_t)z << 20) + pb +
                         (size_t)(n0 - 512 + r0) * 4096 + g * 8;
            #pragma unroll
            for (int it = 0; it < 8; it++) {
                *(uint4*)dp = *(const uint4*)sp;
                sp += 16 * 136;
                dp += 16 * 4096;
            }
        }
    }
}

// ---------------------------------------------------------------------------
// Kernel 4 (FUSED scores + softmax-normalize). grid (32, 32, 2).
// Q pre-scaled: E = exp(acc) directly.
// ---------------------------------------------------------------------------
__global__ __launch_bounds__(256, 2) void scores_mma() {
    extern __shared__ char smraw[];
    const uint32_t smb = smem_u32(smraw);
    desync();
    const int side = blockIdx.z;
    const int m0 = blockIdx.y << 7, n0 = blockIdx.x << 7;

    const int tid = threadIdx.x, lane = tid & 31, wid = tid >> 5;
    const int wm = wid >> 2, wn = wid & 3;
    const int qr = lane >> 2, qc = lane & 3;

    const int lr = tid >> 3, lc = tid & 7;
    const size_t aoff = (size_t)(m0 + lr) * 256 + lc * 8;
    const size_t boff = (size_t)(n0 + lr) * 256 + lc * 8;
    const __half* qbase = g_qh + ((size_t)(side * 4) << 20);
    const __half* kbase = g_kh + ((size_t)((side ^ 1) * 4) << 20);

    const uint32_t sA = smb + lr * 144 + lc * 16;
    const uint32_t sB = sA + 128 * 144;

    auto issue = [&](int s, int c) {
        const uint32_t off = s * STG_B;
        const int b = c >> 2, ko = (c & 3) << 6;
        const __half* a0 = qbase + ((size_t)b << 20) + aoff + ko;
        const __half* b0 = kbase + ((size_t)b << 20) + boff + ko;
        #pragma unroll
        for (int r = 0; r < 4; r++) {
            CP16(sA + off + r * 32 * 144, a0 + (size_t)(r * 32) * 256);
            CP16(sB + off + r * 32 * 144, b0 + (size_t)(r * 32) * 256);
        }
        CP_COMMIT();
    };

    issue(0, 0); issue(1, 1);

    const uint32_t aBase = smb + (wm * 64 + (lane & 15)) * 144 + (lane >> 4) * 16;
    const uint32_t bBase = smb + 128 * 144 +
        (wn * 32 + (lane & 7) + ((lane >> 4) << 3)) * 144 + ((lane >> 3) & 1) * 16;

    float acc[4][4][4];

    int stg = 0, nxt = 2;
    #pragma unroll 1
    for (int c = 0; c < 16; c++) {
        CP_WAIT1();
        __syncthreads();
        const uint32_t off = stg * STG_B;
        if (c + 2 < 16) issue(nxt, c + 2);
        else CP_COMMIT();
        if (++stg == 3) stg = 0;
        if (++nxt == 3) nxt = 0;

        if ((c & 3) == 0) {
            #pragma unroll
            for (int i = 0; i < 4; i++)
                #pragma unroll
                for (int j = 0; j < 4; j++)
                    #pragma unroll
                    for (int t = 0; t < 4; t++) acc[i][j][t] = 0.f;
        }

        #pragma unroll
        for (int k4 = 0; k4 < 4; k4++) {
            const int ks = (k4 + wid) & 3;
            mma_k4(aBase + off + ks * 32, bBase + off + ks * 32, acc);
        }

        if ((c & 3) == 3) {
            const int b = c >> 2;
            const int fs = c % 3;
            __half* stb = (__half*)(smraw + fs * STG_B);   // [128 m][136 pitch]
            __syncthreads();
            #pragma unroll
            for (int i = 0; i < 4; i++) {
                int ml = wm * 64 + i * 16 + qr;
                #pragma unroll
                for (int j = 0; j < 4; j++) {
                    int nl = wn * 32 + j * 8 + qc * 2;
                    *(__half2*)(stb + (size_t)ml * 136 + nl) =
                        __floats2half2_rn(__expf(acc[i][j][0]),
                                          __expf(acc[i][j][1]));
                    *(__half2*)(stb + (size_t)(ml + 8) * 136 + nl) =
                        __floats2half2_rn(__expf(acc[i][j][2]),
                                          __expf(acc[i][j][3]));
                }
            }
            __syncthreads();
            {
                const int r0 = tid >> 4, g = tid & 15;
                const __half* sp = stb + (size_t)r0 * 136 + g * 8;
                __half* dp = g_eh + ((size_t)(side * 4 + b) << 24) +
                             (size_t)(m0 + r0) * 4096 + n0 + g * 8;
                #pragma unroll
                for (int it = 0; it < 8; it++) {
                    *(uint4*)dp = *(const uint4*)sp;
                    sp += 16 * 136;
                    dp += 16 * 4096;
                }
            }
        }
    }

    // in-place normalize: P_b = E_b / sum_b E_b over this CTA's own 4 tiles
    __syncthreads();
    {
        const int r0 = tid >> 4, g = tid & 15;
        __half* p = g_eh + ((size_t)(side * 4) << 24) +
                    (size_t)(m0 + r0) * 4096 + n0 + g * 8;
        #pragma unroll 1
        for (int s8 = 0; s8 < 8; s8++) {
            uint4 e0 = *(const uint4*)(p);
            uint4 e1 = *(const uint4*)(p + (1ull << 24));
            uint4 e2 = *(const uint4*)(p + (2ull << 24));
            uint4 e3 = *(const uint4*)(p + (3ull << 24));
            #pragma unroll
            for (int t = 0; t < 4; t++) {
                float2 f0 = __half22float2(((const __half2*)&e0)[t]);
                float2 f1 = __half22float2(((const __half2*)&e1)[t]);
                float2 f2 = __half22float2(((const __half2*)&e2)[t]);
                float2 f3 = __half22float2(((const __half2*)&e3)[t]);
                float rx = 1.0f / (f0.x + f1.x + f2.x + f3.x);
                float ry = 1.0f / (f0.y + f1.y + f2.y + f3.y);
                ((__half2*)&e0)[t] = __floats2half2_rn(f0.x * rx, f0.y * ry);
                ((__half2*)&e1)[t] = __floats2half2_rn(f1.x * rx, f1.y * ry);
                ((__half2*)&e2)[t] = __floats2half2_rn(f2.x * rx, f2.y * ry);
                ((__half2*)&e3)[t] = __floats2half2_rn(f3.x * rx, f3.y * ry);
            }
            *(uint4*)(p)                = e0;
            *(uint4*)(p + (1ull << 24)) = e1;
            *(uint4*)(p + (2ull << 24)) = e2;
            *(uint4*)(p + (3ull << 24)) = e3;
            p += 16 * 4096;
        }
    }
}

// ---------------------------------------------------------------------------
// Kernel 5 (FINAL): out = x + P @ V'   (V' has Wo folded in)
// grid (2, 32, 8), K = 4096. Epilogue: fp32 transpose + residual -> d_out.
// ---------------------------------------------------------------------------
__global__ __launch_bounds__(256, 2) void pv_mma(const float* __restrict__ xl,
                                                 const float* __restrict__ xr,
                                                 float* __restrict__ outp) {
    extern __shared__ char smraw[];
    const uint32_t smb = smem_u32(smraw);
    desync();
    const int z = blockIdx.z;
    const int m0 = blockIdx.y << 7, n0 = blockIdx.x << 7;

    const __half* Ag = g_eh  + ((size_t)z << 24) + (size_t)m0 * 4096;
    const __half* Bg = g_vth + ((size_t)z << 20) + (size_t)n0 * 4096;

    float acc[4][4][4] = {};
    gemm_core<128>(Ag, Bg, 4096, 4096, smb, acc);

    const int tid = threadIdx.x, wid = tid >> 5, lane = tid & 31;
    const int wm = wid >> 2, wn = wid & 3;
    const int qr = lane >> 2, qc = lane & 3;

    __syncthreads();
    float* st = (float*)smraw;   // [128 m][129]
    #pragma unroll
    for (int i = 0; i < 4; i++) {
        int ml = wm * 64 + i * 16 + qr;
        #pragma unroll
        for (int j = 0; j < 4; j++) {
            int nl = wn * 32 + j * 8 + qc * 2;
            st[(size_t)ml * 129 + nl]           = acc[i][j][0];
            st[(size_t)ml * 129 + nl + 1]       = acc[i][j][1];
            st[(size_t)(ml + 8) * 129 + nl]     = acc[i][j][2];
            st[(size_t)(ml + 8) * 129 + nl + 1] = acc[i][j][3];
        }
    }
    __syncthreads();

    const int side = z >> 2, b = z & 3;
    const float* x = side ? xr : xl;
    {
        const int cl0 = tid >> 7, pl = tid & 127;   // 2 channels, step 2
        float* opb = outp + ((size_t)side << 22) +
                     ((size_t)b * 256 + n0 + cl0) * 4096 + m0 + pl;
        const float* xpb = x + ((size_t)b * 256 + n0 + cl0) * 4096 + m0 + pl;
        const float* sp = st + (size_t)pl * 129 + cl0;
        #pragma unroll
        for (int it = 0; it < 64; it++) {
            opb[0] = xpb[0] + sp[0];
            opb += 2 * 4096;
            xpb += 2 * 4096;
            sp  += 2;
        }
    }
}

// ---------------------------------------------------------------------------
extern "C" void kernel_launch(void* const* d_in, const int* in_sizes, int n_in,
                              void* d_out, int out_size) {
    const float* x_l = (const float*)d_in[0];
    const float* x_r = (const float*)d_in[1];
    const float* Wq  = (const float*)d_in[2];
    const float* Wk  = (const float*)d_in[3];
    const float* Wv  = (const float*)d_in[4];
    const float* Wo  = (const float*)d_in[5];
    const float* g1  = (const float*)d_in[6];
    const float* b1  = (const float*)d_in[7];
    const float* g2  = (const float*)d_in[8];
    const float* b2  = (const float*)d_in[9];
    float* out = (float*)d_out;

    cudaFuncSetAttribute(qkv_mma,    cudaFuncAttributeMaxDynamicSharedMemorySize, SMEM_MMA);
    cudaFuncSetAttribute(scores_mma, cudaFuncAttributeMaxDynamicSharedMemorySize, SMEM_MMA);
    cudaFuncSetAttribute(pv_mma,     cudaFuncAttributeMaxDynamicSharedMemorySize, SMEM_MMA);

    // 1) LayerNorm -> fp16 [p][c]; weight prep (Wq,Wk transpose + Wvo=Wv@Wo)
    ln_kernel<<<dim3(HW / 32, BATCH, 2), 256>>>(x_l, x_r, g1, b1, g2, b2);
    wprep_kernel<<<576, 256>>>(Wq, Wk, Wv, Wo);

    // 2) fused Q/K/V' projections (Q pre-scaled, V' transposed)
    qkv_mma<<<dim3(6, 128, 2), 256, SMEM_MMA>>>();

    // 3) fused scores + batch-softmax normalize (writes P in place)
    scores_mma<<<dim3(32, 32, 2), 256, SMEM_MMA>>>();

    // 4) out = x + P @ V'  (final kernel; residual + transpose epilogue)
    pv_mma<<<dim3(2, 32, 8), 256, SMEM_MMA>>>(x_l, x_r, out);
}